// round 7
// baseline (speedup 1.0000x reference)
#include <cuda_runtime.h>
#include <cuda_fp16.h>

#define DD   256
#define BB   4
#define LXN  512
#define LMN  512

#define TXK  32
#define TMK  64
#define S1H_LD 40
#define S2H_LD 72

__device__ __half g_item1t[BB * DD * LXN];   // [b][d][x] half
__device__ __half g_item2c[BB * DD * LMN];   // [b][d][compacted m] half
__device__ int    g_midx[BB * LMN];          // compacted -> original m
__device__ int    g_pos [BB * LMN];          // original m -> compacted (-1)
__device__ int    g_cnt [BB];

__device__ __forceinline__ __half2 htanh2(__half2 x) {
    unsigned u = *reinterpret_cast<unsigned*>(&x);
    unsigned r;
    asm("tanh.approx.f16x2 %0, %1;" : "=r"(r) : "r"(u));
    return *reinterpret_cast<__half2*>(&r);
}

// ---------------------------------------------------------------------------
// prep: stable mask compaction (one CTA per batch, 4 CTAs total)
// ---------------------------------------------------------------------------
__global__ __launch_bounds__(512) void prep_kernel(const int* __restrict__ mask) {
    const int b = blockIdx.x;
    const int t = threadIdx.x;
    const int lane = t & 31, w = t >> 5;

    int flag = mask[b * LMN + t] != 0;
    unsigned bal = __ballot_sync(0xffffffffu, flag);
    int pre = __popc(bal & ((1u << lane) - 1u));

    __shared__ int wcnt[16], woff[16], s_n;
    if (lane == 0) wcnt[w] = __popc(bal);
    __syncthreads();
    if (t == 0) {
        int s = 0;
        for (int i = 0; i < 16; ++i) { woff[i] = s; s += wcnt[i]; }
        s_n = s;
        g_cnt[b] = s;
    }
    __syncthreads();
    int p = woff[w] + pre;
    g_pos[b * LMN + t] = flag ? p : -1;
    if (flag) g_midx[b * LMN + p] = t;
    __syncthreads();

    // pad g_midx up to the tile boundary (indices read by the tail tile's
    // int4 loads; their stores are predicated off, values just must exist)
    const int n = s_n;
    if (n > 0) {
        const int padded = (n + TMK - 1) / TMK * TMK;
        if (t >= n && t < padded)
            g_midx[b * LMN + t] = g_midx[b * LMN + n - 1];
    }
}

// ---------------------------------------------------------------------------
// Fused NT-GEMM pair (HFMA2 core) + output prefill with -10000 at kernel head
// (store-bound fill overlaps FMA-bound GEMM).
// which==0: x*W1^T + b1 -> g_item1t (dense transposed half)
// which==1: mem*W2^T    -> g_item2c (scatter to compacted column)
// ---------------------------------------------------------------------------
__global__ __launch_bounds__(256) void gemm_h(const float* __restrict__ Xin,
                                              const float* __restrict__ Min,
                                              const float* __restrict__ W1,
                                              const float* __restrict__ W2,
                                              const float* __restrict__ b1,
                                              float4* __restrict__ out4,
                                              int n4) {
    __shared__ __half2 As2[16][76];
    __shared__ __half2 Ws2[16][76];

    const int tid = threadIdx.x;

    // --- output prefill slice
    {
        const int bid = blockIdx.x + 32 * (blockIdx.y + 4 * blockIdx.z);
        const float4 v = make_float4(-10000.f, -10000.f, -10000.f, -10000.f);
        for (int i = bid * 256 + tid; i < n4; i += 256 * 256)
            out4[i] = v;
    }

    const int which = blockIdx.z;
    const float* A = which ? Min : Xin;
    const float* W = which ? W2  : W1;

    const int m0 = blockIdx.x * 64;
    const int n0 = blockIdx.y * 64;
    const int tx = tid & 15;
    const int ty = tid >> 4;
    const int lr = tid >> 2;
    const int lk = (tid & 3) * 8;

    float accf[4][4] = {};
    const __half2 hz = __float2half2_rn(0.f);

    for (int k0 = 0; k0 < DD; k0 += 64) {
        __half2 acc2[4][4];
        #pragma unroll
        for (int i = 0; i < 4; ++i)
            #pragma unroll
            for (int j = 0; j < 4; ++j) acc2[i][j] = hz;

        #pragma unroll
        for (int kk = 0; kk < 64; kk += 32) {
            const int kb = k0 + kk;
            float4 a0 = *(const float4*)&A[(m0 + lr) * DD + kb + lk];
            float4 a1 = *(const float4*)&A[(m0 + lr) * DD + kb + lk + 4];
            float4 w0 = *(const float4*)&W[(n0 + lr) * DD + kb + lk];
            float4 w1 = *(const float4*)&W[(n0 + lr) * DD + kb + lk + 4];
            __syncthreads();
            {
                const int c2 = lk >> 1;
                As2[c2 + 0][lr] = __floats2half2_rn(a0.x, a0.y);
                As2[c2 + 1][lr] = __floats2half2_rn(a0.z, a0.w);
                As2[c2 + 2][lr] = __floats2half2_rn(a1.x, a1.y);
                As2[c2 + 3][lr] = __floats2half2_rn(a1.z, a1.w);
                Ws2[c2 + 0][lr] = __floats2half2_rn(w0.x, w0.y);
                Ws2[c2 + 1][lr] = __floats2half2_rn(w0.z, w0.w);
                Ws2[c2 + 2][lr] = __floats2half2_rn(w1.x, w1.y);
                Ws2[c2 + 3][lr] = __floats2half2_rn(w1.z, w1.w);
            }
            __syncthreads();

            #pragma unroll
            for (int k2 = 0; k2 < 16; ++k2) {
                uint2 au  = *(const uint2*)&As2[k2][tx * 4];
                uint2 au2 = *(const uint2*)&As2[k2][tx * 4 + 2];
                uint2 wu  = *(const uint2*)&Ws2[k2][ty * 4];
                uint2 wu2 = *(const uint2*)&Ws2[k2][ty * 4 + 2];
                __half2 ar[4], wr[4];
                ar[0] = *reinterpret_cast<__half2*>(&au.x);
                ar[1] = *reinterpret_cast<__half2*>(&au.y);
                ar[2] = *reinterpret_cast<__half2*>(&au2.x);
                ar[3] = *reinterpret_cast<__half2*>(&au2.y);
                wr[0] = *reinterpret_cast<__half2*>(&wu.x);
                wr[1] = *reinterpret_cast<__half2*>(&wu.y);
                wr[2] = *reinterpret_cast<__half2*>(&wu2.x);
                wr[3] = *reinterpret_cast<__half2*>(&wu2.y);
                #pragma unroll
                for (int i = 0; i < 4; ++i)
                    #pragma unroll
                    for (int j = 0; j < 4; ++j)
                        acc2[i][j] = __hfma2(ar[i], wr[j], acc2[i][j]);
            }
        }
        #pragma unroll
        for (int i = 0; i < 4; ++i)
            #pragma unroll
            for (int j = 0; j < 4; ++j) {
                float2 t = __half22float2(acc2[i][j]);
                accf[i][j] += t.x + t.y;
            }
    }

    const int r_base = m0 + tx * 4;
    const int bb = r_base >> 9;
    const int lb = r_base & 511;

    if (!which) {
        float4 bv = *(const float4*)&b1[n0 + ty * 4];
        float bj[4] = {bv.x, bv.y, bv.z, bv.w};
        #pragma unroll
        for (int j = 0; j < 4; ++j) {
            int d = n0 + ty * 4 + j;
            __half2 p0 = __halves2half2(__float2half_rn(accf[0][j] + bj[j]),
                                        __float2half_rn(accf[1][j] + bj[j]));
            __half2 p1 = __halves2half2(__float2half_rn(accf[2][j] + bj[j]),
                                        __float2half_rn(accf[3][j] + bj[j]));
            uint2 u;
            u.x = *reinterpret_cast<unsigned*>(&p0);
            u.y = *reinterpret_cast<unsigned*>(&p1);
            *(uint2*)&g_item1t[((bb * DD + d) * LXN) + lb] = u;
        }
    } else {
        int4 pi = *(const int4*)&g_pos[bb * LMN + lb];
        int pos[4] = {pi.x, pi.y, pi.z, pi.w};
        #pragma unroll
        for (int j = 0; j < 4; ++j) {
            int d = n0 + ty * 4 + j;
            __half* dst = g_item2c + (bb * DD + d) * LMN;
            #pragma unroll
            for (int i = 0; i < 4; ++i)
                if (pos[i] >= 0)
                    dst[pos[i]] = __float2half_rn(accf[i][j]);
        }
    }
}

// ---------------------------------------------------------------------------
// attn over ACTIVE m-columns. Hybrid tanh: even d -> MUFU tanh.approx.f16x2,
// odd d -> degree-5 odd polynomial on FMA/ALU pipes (clamp +-2.5).
// All tiles use natural aligned m0; tail columns >= n_act are computed on
// garbage-but-in-bounds data and their stores are predicated off.
// ---------------------------------------------------------------------------
extern __shared__ __align__(16) char smem_raw[];

__device__ __forceinline__ __half2 ptanh2(__half2 x, __half2 clo, __half2 chi,
                                          __half2 ca, __half2 cb, __half2 cc) {
    __half2 xc = __hmax2(__hmin2(x, chi), clo);          // alu
    __half2 t  = __hmul2(xc, xc);                        // fma
    __half2 p  = __hfma2(t, __hfma2(t, cc, cb), ca);     // 2 fma
    return __hmul2(xc, p);                               // fma
}

__global__ __launch_bounds__(256) void attn_kernel(const float* __restrict__ Wt,
                                                   float* __restrict__ out) {
    const int b  = blockIdx.z;
    const int m0 = blockIdx.y * TMK;
    const int n_act = g_cnt[b];
    if (m0 >= n_act) return;

    __half*   s1   = (__half*)smem_raw;               // [DD][S1H_LD]
    __half*   s2   = s1 + DD * S1H_LD;                // [DD][S2H_LD]
    unsigned* swt  = (unsigned*)(s2 + DD * S2H_LD);   // [DD] half2 splat

    const int tid = threadIdx.x;
    const int x0 = blockIdx.x * TXK;

    {
        const int d = tid;
        const float4* p1 = (const float4*)(g_item1t + (b * DD + d) * LXN + x0);
        float4* q1 = (float4*)(s1 + d * S1H_LD);
        #pragma unroll
        for (int j = 0; j < 4; ++j) q1[j] = p1[j];

        const float4* p2 = (const float4*)(g_item2c + (b * DD + d) * LMN + m0);
        float4* q2 = (float4*)(s2 + d * S2H_LD);
        #pragma unroll
        for (int j = 0; j < 8; ++j) q2[j] = p2[j];

        __half h = __float2half_rn(Wt[d]);
        __half2 hh = __halves2half2(h, h);
        swt[d] = *reinterpret_cast<unsigned*>(&hh);
    }
    __syncthreads();

    const int tx = tid & 15;
    const int tm = tid >> 4;
    const __half* s1p = s1 + tx * 2;
    const __half* s2p = s2 + tm * 4;

    const __half2 hz  = __float2half2_rn(0.f);
    const __half2 chi = __float2half2_rn(2.5f);
    const __half2 clo = __float2half2_rn(-2.5f);
    const __half2 ca  = __float2half2_rn(0.97444f);
    const __half2 cb  = __float2half2_rn(-0.20549f);
    const __half2 cc  = __float2half2_rn(0.018033f);

    float2 f00 = {0.f, 0.f}, f01 = {0.f, 0.f}, f10 = {0.f, 0.f}, f11 = {0.f, 0.f};

    #pragma unroll 1
    for (int d0 = 0; d0 < DD; d0 += 64) {
        __half2 a00 = hz, a01 = hz, a10 = hz, a11 = hz;
        #pragma unroll 8
        for (int d = d0; d < d0 + 64; ++d) {
            __half2 a = *(const __half2*)(s1p + d * S1H_LD);
            uint2 mv  = *(const uint2*)(s2p + d * S2H_LD);
            __half2 m01 = *reinterpret_cast<__half2*>(&mv.x);
            __half2 m23 = *reinterpret_cast<__half2*>(&mv.y);
            unsigned wu = swt[d];
            __half2 wt2 = *reinterpret_cast<__half2*>(&wu);
            __half2 aa0 = __low2half2(a);
            __half2 aa1 = __high2half2(a);
            if (d & 1) {   // polynomial path (FMA/ALU pipes)
                a00 = __hfma2(ptanh2(__hadd2(aa0, m01), clo, chi, ca, cb, cc), wt2, a00);
                a01 = __hfma2(ptanh2(__hadd2(aa0, m23), clo, chi, ca, cb, cc), wt2, a01);
                a10 = __hfma2(ptanh2(__hadd2(aa1, m01), clo, chi, ca, cb, cc), wt2, a10);
                a11 = __hfma2(ptanh2(__hadd2(aa1, m23), clo, chi, ca, cb, cc), wt2, a11);
            } else {       // MUFU path
                a00 = __hfma2(htanh2(__hadd2(aa0, m01)), wt2, a00);
                a01 = __hfma2(htanh2(__hadd2(aa0, m23)), wt2, a01);
                a10 = __hfma2(htanh2(__hadd2(aa1, m01)), wt2, a10);
                a11 = __hfma2(htanh2(__hadd2(aa1, m23)), wt2, a11);
            }
        }
        float2 t;
        t = __half22float2(a00); f00.x += t.x; f00.y += t.y;
        t = __half22float2(a01); f01.x += t.x; f01.y += t.y;
        t = __half22float2(a10); f10.x += t.x; f10.y += t.y;
        t = __half22float2(a11); f11.x += t.x; f11.y += t.y;
    }

    // predicated scatter-store: only truly active columns write
    const int c0 = m0 + tm * 4;
    int4 mi = *(const int4*)&g_midx[b * LMN + c0];   // m0, tm*4 both 4-aligned
    bool a0v = (c0 + 0) < n_act, a1v = (c0 + 1) < n_act;
    bool a2v = (c0 + 2) < n_act, a3v = (c0 + 3) < n_act;
    const int x = x0 + tx * 2;
    float* r0 = out + (b * LXN + x) * (long)LMN;
    float* r1 = r0 + LMN;
    if (a0v) { r0[mi.x] = f00.x; r1[mi.x] = f10.x; }
    if (a1v) { r0[mi.y] = f00.y; r1[mi.y] = f10.y; }
    if (a2v) { r0[mi.z] = f01.x; r1[mi.z] = f11.x; }
    if (a3v) { r0[mi.w] = f01.y; r1[mi.w] = f11.y; }
}

// ---------------------------------------------------------------------------

extern "C" void kernel_launch(void* const* d_in, const int* in_sizes, int n_in,
                              void* d_out, int out_size) {
    const float* x      = (const float*)d_in[0];
    const float* memory = (const float*)d_in[1];
    const int*   mask   = (const int*)d_in[2];
    const float* W1     = (const float*)d_in[3];
    const float* b1     = (const float*)d_in[4];
    const float* W2     = (const float*)d_in[5];
    const float* Wt     = (const float*)d_in[6];
    float* out = (float*)d_out;

    // 1) mask compaction (4 tiny CTAs)
    prep_kernel<<<BB, 512>>>(mask);

    // 2) fused projections + output prefill
    dim3 ggrid(2048 / 64, DD / 64, 2);
    gemm_h<<<ggrid, 256>>>(x, memory, W1, W2, b1, (float4*)out, out_size / 4);

    // 3) attention over active columns only (hybrid MUFU/poly tanh)
    const int smem_bytes = (DD * S1H_LD + DD * S2H_LD) * 2 + DD * 4;
    cudaFuncSetAttribute(attn_kernel,
                         cudaFuncAttributeMaxDynamicSharedMemorySize, smem_bytes);
    dim3 agrid(LXN / TXK, LMN / TMK, BB);
    attn_kernel<<<agrid, 256, smem_bytes>>>(Wt, out);
}

// round 10
// speedup vs baseline: 1.5555x; 1.5555x over previous
#include <cuda_runtime.h>
#include <cuda_fp16.h>

#define DD   256
#define BB   4
#define LXN  512
#define LMN  512

#define TXK  32
#define TMK  64
#define S1LD 34      // fp32 leading dim; rows are 8B-aligned -> float2 access
#define S2LD 68      // fp32 leading dim; rows are 16B-aligned -> float4 access

__device__ float g_item1t[BB * DD * LXN];   // [b][d][x] fp32
__device__ float g_item2c[BB * DD * LMN];   // [b][d][compacted m] fp32
__device__ int   g_midx[BB * LMN];          // compacted -> original m
__device__ int   g_pos [BB * LMN];          // original m -> compacted (-1)
__device__ int   g_cnt [BB];

__device__ __forceinline__ float fast_tanh(float x) {
    float y;
    asm("tanh.approx.f32 %0, %1;" : "=f"(y) : "f"(x));
    return y;
}

// clamp +-2.5 poly: x*(a + b*x^2 + c*x^4); max abs err ~0.08, exact at clamp
__device__ __forceinline__ float ptanh(float x) {
    float xc = fminf(fmaxf(x, -2.5f), 2.5f);
    float t  = xc * xc;
    return xc * fmaf(t, fmaf(t, 0.018033f, -0.20549f), 0.97444f);
}

// ---------------------------------------------------------------------------
// prep: blocks 0..BB-1 compact the mask; remaining blocks fill out = -10000
// ---------------------------------------------------------------------------
__global__ __launch_bounds__(512) void prep_kernel(const int* __restrict__ mask,
                                                   float4* __restrict__ out,
                                                   int n4) {
    if (blockIdx.x < BB) {
        const int b = blockIdx.x;
        const int t = threadIdx.x;
        const int lane = t & 31, w = t >> 5;

        int flag = mask[b * LMN + t] != 0;
        unsigned bal = __ballot_sync(0xffffffffu, flag);
        int pre = __popc(bal & ((1u << lane) - 1u));

        __shared__ int wcnt[16], woff[16], s_n;
        if (lane == 0) wcnt[w] = __popc(bal);
        __syncthreads();
        if (t == 0) {
            int s = 0;
            for (int i = 0; i < 16; ++i) { woff[i] = s; s += wcnt[i]; }
            s_n = s;
            g_cnt[b] = s;
        }
        __syncthreads();
        int p = woff[w] + pre;
        g_pos[b * LMN + t] = flag ? p : -1;
        if (flag) g_midx[b * LMN + p] = t;
        __syncthreads();

        const int n = s_n;   // pad indices for the tail tile's int4 reads
        if (n > 0) {
            const int padded = (n + TMK - 1) / TMK * TMK;
            if (t >= n && t < padded)
                g_midx[b * LMN + t] = g_midx[b * LMN + n - 1];
        }
    } else {
        const float4 v = make_float4(-10000.f, -10000.f, -10000.f, -10000.f);
        const int stride = (gridDim.x - BB) * blockDim.x;
        for (int i = (blockIdx.x - BB) * blockDim.x + threadIdx.x; i < n4;
             i += stride)
            out[i] = v;
    }
}

// ---------------------------------------------------------------------------
// Fused NT-GEMM pair, HFMA2 core, fp32 outputs.
// which==0: x*W1^T + b1 -> g_item1t (transposed [b][d][x] fp32)
// which==1: mem*W2^T    -> g_item2c (scatter to compacted column, fp32)
// ---------------------------------------------------------------------------
__global__ __launch_bounds__(256) void gemm_h(const float* __restrict__ Xin,
                                              const float* __restrict__ Min,
                                              const float* __restrict__ W1,
                                              const float* __restrict__ W2,
                                              const float* __restrict__ b1) {
    __shared__ __half2 As2[16][76];
    __shared__ __half2 Ws2[16][76];

    const int which = blockIdx.z;
    const float* A = which ? Min : Xin;
    const float* W = which ? W2  : W1;

    const int tid = threadIdx.x;
    const int m0 = blockIdx.x * 64;
    const int n0 = blockIdx.y * 64;
    const int tx = tid & 15;
    const int ty = tid >> 4;
    const int lr = tid >> 2;
    const int lk = (tid & 3) * 8;

    float accf[4][4] = {};
    const __half2 hz = __float2half2_rn(0.f);

    for (int k0 = 0; k0 < DD; k0 += 64) {
        __half2 acc2[4][4];
        #pragma unroll
        for (int i = 0; i < 4; ++i)
            #pragma unroll
            for (int j = 0; j < 4; ++j) acc2[i][j] = hz;

        #pragma unroll
        for (int kk = 0; kk < 64; kk += 32) {
            const int kb = k0 + kk;
            float4 a0 = *(const float4*)&A[(m0 + lr) * DD + kb + lk];
            float4 a1 = *(const float4*)&A[(m0 + lr) * DD + kb + lk + 4];
            float4 w0 = *(const float4*)&W[(n0 + lr) * DD + kb + lk];
            float4 w1 = *(const float4*)&W[(n0 + lr) * DD + kb + lk + 4];
            __syncthreads();
            {
                const int c2 = lk >> 1;
                As2[c2 + 0][lr] = __floats2half2_rn(a0.x, a0.y);
                As2[c2 + 1][lr] = __floats2half2_rn(a0.z, a0.w);
                As2[c2 + 2][lr] = __floats2half2_rn(a1.x, a1.y);
                As2[c2 + 3][lr] = __floats2half2_rn(a1.z, a1.w);
                Ws2[c2 + 0][lr] = __floats2half2_rn(w0.x, w0.y);
                Ws2[c2 + 1][lr] = __floats2half2_rn(w0.z, w0.w);
                Ws2[c2 + 2][lr] = __floats2half2_rn(w1.x, w1.y);
                Ws2[c2 + 3][lr] = __floats2half2_rn(w1.z, w1.w);
            }
            __syncthreads();

            #pragma unroll
            for (int k2 = 0; k2 < 16; ++k2) {
                uint2 au  = *(const uint2*)&As2[k2][tx * 4];
                uint2 au2 = *(const uint2*)&As2[k2][tx * 4 + 2];
                uint2 wu  = *(const uint2*)&Ws2[k2][ty * 4];
                uint2 wu2 = *(const uint2*)&Ws2[k2][ty * 4 + 2];
                __half2 ar[4], wr[4];
                ar[0] = *reinterpret_cast<__half2*>(&au.x);
                ar[1] = *reinterpret_cast<__half2*>(&au.y);
                ar[2] = *reinterpret_cast<__half2*>(&au2.x);
                ar[3] = *reinterpret_cast<__half2*>(&au2.y);
                wr[0] = *reinterpret_cast<__half2*>(&wu.x);
                wr[1] = *reinterpret_cast<__half2*>(&wu.y);
                wr[2] = *reinterpret_cast<__half2*>(&wu2.x);
                wr[3] = *reinterpret_cast<__half2*>(&wu2.y);
                #pragma unroll
                for (int i = 0; i < 4; ++i)
                    #pragma unroll
                    for (int j = 0; j < 4; ++j)
                        acc2[i][j] = __hfma2(ar[i], wr[j], acc2[i][j]);
            }
        }
        #pragma unroll
        for (int i = 0; i < 4; ++i)
            #pragma unroll
            for (int j = 0; j < 4; ++j) {
                float2 t = __half22float2(acc2[i][j]);
                accf[i][j] += t.x + t.y;
            }
    }

    const int r_base = m0 + tx * 4;
    const int bb = r_base >> 9;
    const int lb = r_base & 511;

    if (!which) {
        float4 bv = *(const float4*)&b1[n0 + ty * 4];
        float bj[4] = {bv.x, bv.y, bv.z, bv.w};
        #pragma unroll
        for (int j = 0; j < 4; ++j) {
            int d = n0 + ty * 4 + j;
            float4 v;
            v.x = accf[0][j] + bj[j];
            v.y = accf[1][j] + bj[j];
            v.z = accf[2][j] + bj[j];
            v.w = accf[3][j] + bj[j];
            *(float4*)&g_item1t[((bb * DD + d) * LXN) + lb] = v;
        }
    } else {
        int4 pi = *(const int4*)&g_pos[bb * LMN + lb];
        int pos[4] = {pi.x, pi.y, pi.z, pi.w};
        #pragma unroll
        for (int j = 0; j < 4; ++j) {
            int d = n0 + ty * 4 + j;
            float* dst = g_item2c + (bb * DD + d) * LMN;
            #pragma unroll
            for (int i = 0; i < 4; ++i)
                if (pos[i] >= 0)
                    dst[pos[i]] = accf[i][j];
        }
    }
}

// ---------------------------------------------------------------------------
// attn over ACTIVE m-columns, fp32. Hybrid tanh: d%4==3 -> fp32 polynomial
// (FMA pipe), else MUFU tanh.approx.f32. Tail stores predicated on n_act.
// s1 rows use float2 access (S1LD*4 = 136 B: 8B-aligned, NOT 16B-aligned).
// ---------------------------------------------------------------------------
extern __shared__ __align__(16) float smem_f[];

__global__ __launch_bounds__(256) void attn_kernel(const float* __restrict__ Wt,
                                                   float* __restrict__ out) {
    const int b  = blockIdx.z;
    const int m0 = blockIdx.y * TMK;
    const int n_act = g_cnt[b];
    if (m0 >= n_act) return;

    float* s1  = smem_f;                 // [DD][S1LD]
    float* s2  = s1 + DD * S1LD;         // [DD][S2LD]
    float* swt = s2 + DD * S2LD;         // [DD]

    const int tid = threadIdx.x;
    const int x0 = blockIdx.x * TXK;

    {
        const int d = tid;
        // s1 row: 32 floats via float2 (row base 8B-aligned only)
        const float2* p1 = (const float2*)(g_item1t + (b * DD + d) * LXN + x0);
        float2* q1 = (float2*)(s1 + d * S1LD);
        #pragma unroll
        for (int j = 0; j < 16; ++j) q1[j] = p1[j];

        // s2 row: 64 floats via float4 (row base 16B-aligned)
        const float4* p2 = (const float4*)(g_item2c + (b * DD + d) * LMN + m0);
        float* q2 = s2 + d * S2LD;
        #pragma unroll
        for (int j = 0; j < 16; ++j) *(float4*)(q2 + j * 4) = p2[j];

        swt[d] = Wt[d];
    }
    __syncthreads();

    const int tx = tid & 15;
    const int tm = tid >> 4;
    const float* s1p = s1 + tx * 2;
    const float* s2p = s2 + tm * 4;

    float acc[2][4] = {};

    #pragma unroll 1
    for (int d0 = 0; d0 < DD; d0 += 4) {
        #pragma unroll
        for (int dd = 0; dd < 4; ++dd) {
            const int d = d0 + dd;
            float  w  = swt[d];
            float2 a  = *(const float2*)(s1p + d * S1LD);
            float4 m4 = *(const float4*)(s2p + d * S2LD);
            if (dd != 3) {   // MUFU path (3 of 4)
                acc[0][0] += fast_tanh(a.x + m4.x) * w;
                acc[0][1] += fast_tanh(a.x + m4.y) * w;
                acc[0][2] += fast_tanh(a.x + m4.z) * w;
                acc[0][3] += fast_tanh(a.x + m4.w) * w;
                acc[1][0] += fast_tanh(a.y + m4.x) * w;
                acc[1][1] += fast_tanh(a.y + m4.y) * w;
                acc[1][2] += fast_tanh(a.y + m4.z) * w;
                acc[1][3] += fast_tanh(a.y + m4.w) * w;
            } else {         // polynomial path (1 of 4) on the FMA/ALU pipes
                acc[0][0] += ptanh(a.x + m4.x) * w;
                acc[0][1] += ptanh(a.x + m4.y) * w;
                acc[0][2] += ptanh(a.x + m4.z) * w;
                acc[0][3] += ptanh(a.x + m4.w) * w;
                acc[1][0] += ptanh(a.y + m4.x) * w;
                acc[1][1] += ptanh(a.y + m4.y) * w;
                acc[1][2] += ptanh(a.y + m4.z) * w;
                acc[1][3] += ptanh(a.y + m4.w) * w;
            }
        }
    }

    // predicated scatter-store: only truly active columns write
    const int c0 = m0 + tm * 4;
    int4 mi = *(const int4*)&g_midx[b * LMN + c0];
    bool v0 = (c0 + 0) < n_act, v1 = (c0 + 1) < n_act;
    bool v2 = (c0 + 2) < n_act, v3 = (c0 + 3) < n_act;
    const int x = x0 + tx * 2;
    float* r0 = out + (b * LXN + x) * (long)LMN;
    float* r1 = r0 + LMN;
    if (v0) { r0[mi.x] = acc[0][0]; r1[mi.x] = acc[1][0]; }
    if (v1) { r0[mi.y] = acc[0][1]; r1[mi.y] = acc[1][1]; }
    if (v2) { r0[mi.z] = acc[0][2]; r1[mi.z] = acc[1][2]; }
    if (v3) { r0[mi.w] = acc[0][3]; r1[mi.w] = acc[1][3]; }
}

// ---------------------------------------------------------------------------

extern "C" void kernel_launch(void* const* d_in, const int* in_sizes, int n_in,
                              void* d_out, int out_size) {
    const float* x      = (const float*)d_in[0];
    const float* memory = (const float*)d_in[1];
    const int*   mask   = (const int*)d_in[2];
    const float* W1     = (const float*)d_in[3];
    const float* b1     = (const float*)d_in[4];
    const float* W2     = (const float*)d_in[5];
    const float* Wt     = (const float*)d_in[6];
    float* out = (float*)d_out;

    // 1) mask compaction + output prefill (fused, one launch)
    prep_kernel<<<512, 512>>>(mask, (float4*)out, out_size / 4);

    // 2) fused projections (HFMA2 core, fp32 out; item2 scatters compacted)
    dim3 ggrid(2048 / 64, DD / 64, 2);
    gemm_h<<<ggrid, 256>>>(x, memory, W1, W2, b1);

    // 3) attention over active columns (fp32, 3:1 MUFU:poly hybrid)
    const int smem_bytes = (DD * S1LD + DD * S2LD + DD) * 4;
    cudaFuncSetAttribute(attn_kernel,
                         cudaFuncAttributeMaxDynamicSharedMemorySize, smem_bytes);
    dim3 agrid(LXN / TXK, LMN / TMK, BB);
    attn_kernel<<<agrid, 256, smem_bytes>>>(Wt, out);
}